// round 1
// baseline (speedup 1.0000x reference)
#include <cuda_runtime.h>

#define N_BASES 5
#define C_IN    128
#define C_OUT   128
#define HW      56
#define BATCH   32
#define WELEMS  (C_OUT * C_IN * 9)      // 147456 per base
#define XS_STRIDE 12                    // padded row stride (bank-conflict-free)
#define CI_HALF 64                      // channels per smem stage
#define KC      8                       // k-steps (input channels) per weight chunk
#define WCHUNK  (KC * C_OUT * 2)        // 2048 floats = 8 KB per buffer

// -------- device scratch (no allocations allowed) --------
__device__ float g_m[N_BASES];
__device__ float g_weff[9 * C_IN * C_OUT * 2];   // [kidx][cin][cout][2], value duplicated

// -------- packed f32x2 helpers --------
__device__ __forceinline__ void ffma2(unsigned long long& d, unsigned long long a,
                                      unsigned long long b) {
    asm("fma.rn.f32x2 %0, %1, %2, %0;" : "+l"(d) : "l"(a), "l"(b));
}
__device__ __forceinline__ unsigned long long pack2(float a, float b) {
    unsigned long long r;
    asm("mov.b64 %0, {%1, %2};" : "=l"(r) : "r"(__float_as_int(a)), "r"(__float_as_int(b)));
    return r;
}
__device__ __forceinline__ void unpack2(unsigned long long v, float& a, float& b) {
    int lo, hi;
    asm("mov.b64 {%0, %1}, %2;" : "=r"(lo), "=r"(hi) : "l"(v));
    a = __int_as_float(lo);
    b = __int_as_float(hi);
}

// ================= kernel 1: per-base mean(|w|) =================
__global__ void mean_abs_kernel(const float* __restrict__ w) {
    int n = blockIdx.x;
    const float* wn = w + (size_t)n * WELEMS;
    float s = 0.f;
    for (int i = threadIdx.x; i < WELEMS; i += 256) s += fabsf(wn[i]);
    __shared__ float red[256];
    red[threadIdx.x] = s;
    __syncthreads();
    for (int off = 128; off > 0; off >>= 1) {
        if (threadIdx.x < off) red[threadIdx.x] += red[threadIdx.x + off];
        __syncthreads();
    }
    if (threadIdx.x == 0) g_m[n] = red[0] / (float)WELEMS;
}

// ================= kernel 2: effective weight, duplicated pairs =================
// g_weff[((kidx*C_IN + i)*C_OUT + o)*2 + {0,1}] = sum_n scales[n]*m[n]*sign(w[n,o,i,kidx])
__global__ void build_weff_kernel(const float* __restrict__ w,
                                  const float* __restrict__ scales) {
    int idx = blockIdx.x * blockDim.x + threadIdx.x;  // idx = (kidx*C_IN + i)*C_OUT + o
    if (idx >= WELEMS) return;
    int o = idx % C_OUT;
    int t = idx / C_OUT;
    int i = t % C_IN;
    int kidx = t / C_IN;
    float v = 0.f;
#pragma unroll
    for (int n = 0; n < N_BASES; n++) {
        float wv = w[(((size_t)n * C_OUT + o) * C_IN + i) * 9 + kidx];
        float sg = (wv > 0.f) ? 1.f : ((wv < 0.f) ? -1.f : 0.f);
        v += scales[n] * g_m[n] * sg;
    }
    g_weff[idx * 2 + 0] = v;
    g_weff[idx * 2 + 1] = v;
}

// ================= conv kernel =================
__device__ __forceinline__ void issue_chunk(float* sdst_base, const float* gsrc_base,
                                            int tid) {
    unsigned sdst = (unsigned)__cvta_generic_to_shared(sdst_base) + (unsigned)tid * 16u;
    const float* gsrc = gsrc_base + tid * 4;
#pragma unroll
    for (int j = 0; j < 4; j++) {
        asm volatile("cp.async.cg.shared.global [%0], [%1], 16;" ::"r"(sdst + j * 2048u),
                     "l"(gsrc + j * 512));
    }
    asm volatile("cp.async.commit_group;" ::: "memory");
}

__device__ __forceinline__ void fma_tile(unsigned long long* acc, unsigned long long x0,
                                         unsigned long long x1, unsigned long long x2,
                                         unsigned long long x3, const float* wb) {
    ulonglong2 w01 = *(const ulonglong2*)(wb + 0);
    ulonglong2 w23 = *(const ulonglong2*)(wb + 4);
    ulonglong2 w45 = *(const ulonglong2*)(wb + 8);
    ulonglong2 w67 = *(const ulonglong2*)(wb + 12);
    ffma2(acc[0], x0, w01.x);  ffma2(acc[1], x1, w01.x);
    ffma2(acc[2], x2, w01.x);  ffma2(acc[3], x3, w01.x);
    ffma2(acc[4], x0, w01.y);  ffma2(acc[5], x1, w01.y);
    ffma2(acc[6], x2, w01.y);  ffma2(acc[7], x3, w01.y);
    ffma2(acc[8], x0, w23.x);  ffma2(acc[9], x1, w23.x);
    ffma2(acc[10], x2, w23.x); ffma2(acc[11], x3, w23.x);
    ffma2(acc[12], x0, w23.y); ffma2(acc[13], x1, w23.y);
    ffma2(acc[14], x2, w23.y); ffma2(acc[15], x3, w23.y);
    ffma2(acc[16], x0, w45.x); ffma2(acc[17], x1, w45.x);
    ffma2(acc[18], x2, w45.x); ffma2(acc[19], x3, w45.x);
    ffma2(acc[20], x0, w45.y); ffma2(acc[21], x1, w45.y);
    ffma2(acc[22], x2, w45.y); ffma2(acc[23], x3, w45.y);
    ffma2(acc[24], x0, w67.x); ffma2(acc[25], x1, w67.x);
    ffma2(acc[26], x2, w67.x); ffma2(acc[27], x3, w67.x);
    ffma2(acc[28], x0, w67.y); ffma2(acc[29], x1, w67.y);
    ffma2(acc[30], x2, w67.y); ffma2(acc[31], x3, w67.y);
}

__global__ void __launch_bounds__(128, 4)
conv_kernel(const float* __restrict__ x, float* __restrict__ out) {
    __shared__ __align__(16) float xs[CI_HALF * 10 * XS_STRIDE];  // 30720 B
    __shared__ __align__(16) float ws[2 * WCHUNK];                 // 16384 B

    const int tid = threadIdx.x;
    const int og = tid >> 3;  // 0..15 : o-group (8 outputs each)
    const int pg = tid & 7;   // 0..7  : output row within tile
    const int tx = blockIdx.x, ty = blockIdx.y, b = blockIdx.z;
    const int gy0 = ty * 8 - 1;
    const int gx0 = tx * 8 - 1;

    unsigned long long acc[32];
#pragma unroll
    for (int j = 0; j < 32; j++) acc[j] = 0ULL;

    int buf = 0;
    issue_chunk(ws, g_weff, tid);  // (h=0, kidx=0, ic=0)

#pragma unroll 1
    for (int h = 0; h < 2; h++) {
        // ---- stage x patch for channels [h*64, h*64+64) (pad value = 1.0) ----
        const float* xh = x + ((size_t)b * C_IN + h * CI_HALF) * HW * HW;
#pragma unroll 1
        for (int idx = tid; idx < CI_HALF * 100; idx += 128) {
            int i = idx / 100;
            int rem = idx - i * 100;
            int r = rem / 10;
            int c = rem - r * 10;
            int gy = gy0 + r, gx = gx0 + c;
            float v = 1.0f;
            if ((unsigned)gy < HW && (unsigned)gx < HW)
                v = xh[(i * HW + gy) * HW + gx];
            xs[i * (10 * XS_STRIDE) + r * XS_STRIDE + c] = v;
        }
        // visibility of xs guaranteed by the __syncthreads() before first compute below

#pragma unroll 1
        for (int kidx = 0; kidx < 9; kidx++) {
            const int ky = kidx / 3;
            const int kx = kidx - 3 * ky;
            const float* xb = xs + (pg + ky) * XS_STRIDE + kx;
#pragma unroll 1
            for (int ic = 0; ic < 8; ic++) {
                // prefetch next chunk into the other buffer
                int nic = ic + 1, nk = kidx, nh = h;
                if (nic == 8) { nic = 0; if (++nk == 9) { nk = 0; nh++; } }
                if (nh < 2) {
                    issue_chunk(ws + (buf ^ 1) * WCHUNK,
                                g_weff + ((size_t)(nk * C_IN + nh * CI_HALF + nic * KC)) *
                                             (C_OUT * 2),
                                tid);
                    asm volatile("cp.async.wait_group 1;" ::: "memory");
                } else {
                    asm volatile("cp.async.wait_group 0;" ::: "memory");
                }
                __syncthreads();

                const float* wbase = ws + buf * WCHUNK + og * 16;
                const float* xc = xb + ic * KC * (10 * XS_STRIDE);
                if (kx != 1) {
                    // 8-byte aligned packed loads (kx even)
#pragma unroll
                    for (int kk = 0; kk < KC; kk++) {
                        const float* xr = xc + kk * (10 * XS_STRIDE);
                        unsigned long long x0 = *(const unsigned long long*)(xr + 0);
                        unsigned long long x1 = *(const unsigned long long*)(xr + 2);
                        unsigned long long x2 = *(const unsigned long long*)(xr + 4);
                        unsigned long long x3 = *(const unsigned long long*)(xr + 6);
                        fma_tile(acc, x0, x1, x2, x3, wbase + kk * (C_OUT * 2));
                    }
                } else {
                    // odd offset: scalar loads + pack
#pragma unroll
                    for (int kk = 0; kk < KC; kk++) {
                        const float* xr = xc + kk * (10 * XS_STRIDE);
                        float f0 = xr[0], f1 = xr[1], f2 = xr[2], f3 = xr[3];
                        float f4 = xr[4], f5 = xr[5], f6 = xr[6], f7 = xr[7];
                        unsigned long long x0 = pack2(f0, f1);
                        unsigned long long x1 = pack2(f2, f3);
                        unsigned long long x2 = pack2(f4, f5);
                        unsigned long long x3 = pack2(f6, f7);
                        fma_tile(acc, x0, x1, x2, x3, wbase + kk * (C_OUT * 2));
                    }
                }
                __syncthreads();
                buf ^= 1;
            }
        }
    }

    // ---- epilogue: 8 o x 8 pos per thread ----
    const int oy = ty * 8 + pg;
    const int ox = tx * 8;
#pragma unroll
    for (int oo = 0; oo < 8; oo++) {
        int o = og * 8 + oo;
        float* orow = out + (((size_t)b * C_OUT + o) * HW + oy) * HW + ox;
#pragma unroll
        for (int p = 0; p < 4; p++) {
            float a, bb;
            unpack2(acc[oo * 4 + p], a, bb);
            *(float2*)(orow + 2 * p) = make_float2(a, bb);
        }
    }
}

// ================= launcher =================
extern "C" void kernel_launch(void* const* d_in, const int* in_sizes, int n_in,
                              void* d_out, int out_size) {
    const float* x = (const float*)d_in[0];        // [32,128,56,56]
    const float* w = (const float*)d_in[1];        // [5,128,128,3,3]
    const float* scales = (const float*)d_in[2];   // [5]
    float* out = (float*)d_out;                    // [32,128,56,56]

    mean_abs_kernel<<<N_BASES, 256>>>(w);
    build_weff_kernel<<<(WELEMS + 255) / 256, 256>>>(w, scales);
    conv_kernel<<<dim3(7, 7, BATCH), 128>>>(x, out);
}

// round 2
// speedup vs baseline: 1.5959x; 1.5959x over previous
#include <cuda_runtime.h>

#define N_BASES 5
#define C_IN    128
#define C_OUT   128
#define HW      56
#define BATCH   32
#define WELEMS  (C_OUT * C_IN * 9)      // 147456 per base
#define XS_STRIDE 12                    // padded row stride (bank-conflict-free)
#define CI_HALF 64                      // channels per smem stage
#define KC      8                       // k-steps (input channels) per weight chunk
#define WCHUNK  (KC * C_OUT * 2)        // 2048 floats = 8 KB per buffer

// -------- device scratch (no allocations allowed) --------
__device__ float g_m[N_BASES];
__device__ float g_weff[9 * C_IN * C_OUT * 2];   // [kidx][cin][cout][2], value duplicated

// -------- packed f32x2 helpers --------
__device__ __forceinline__ void ffma2(unsigned long long& d, unsigned long long a,
                                      unsigned long long b) {
    asm("fma.rn.f32x2 %0, %1, %2, %0;" : "+l"(d) : "l"(a), "l"(b));
}
__device__ __forceinline__ unsigned long long pack2(float a, float b) {
    unsigned long long r;
    asm("mov.b64 %0, {%1, %2};" : "=l"(r) : "r"(__float_as_int(a)), "r"(__float_as_int(b)));
    return r;
}
__device__ __forceinline__ void unpack2(unsigned long long v, float& a, float& b) {
    int lo, hi;
    asm("mov.b64 {%0, %1}, %2;" : "=r"(lo), "=r"(hi) : "l"(v));
    a = __int_as_float(lo);
    b = __int_as_float(hi);
}

// ================= kernel 1: per-base mean(|w|) =================
__global__ void mean_abs_kernel(const float* __restrict__ w) {
    int n = blockIdx.x;
    const float* wn = w + (size_t)n * WELEMS;
    float s = 0.f;
    for (int i = threadIdx.x; i < WELEMS; i += 256) s += fabsf(wn[i]);
    __shared__ float red[256];
    red[threadIdx.x] = s;
    __syncthreads();
    for (int off = 128; off > 0; off >>= 1) {
        if (threadIdx.x < off) red[threadIdx.x] += red[threadIdx.x + off];
        __syncthreads();
    }
    if (threadIdx.x == 0) g_m[n] = red[0] / (float)WELEMS;
}

// ================= kernel 2: effective weight, duplicated pairs =================
// g_weff[((kidx*C_IN + i)*C_OUT + o)*2 + {0,1}] = sum_n scales[n]*m[n]*sign(w[n,o,i,kidx])
__global__ void build_weff_kernel(const float* __restrict__ w,
                                  const float* __restrict__ scales) {
    int idx = blockIdx.x * blockDim.x + threadIdx.x;  // idx = (kidx*C_IN + i)*C_OUT + o
    if (idx >= WELEMS) return;
    int o = idx % C_OUT;
    int t = idx / C_OUT;
    int i = t % C_IN;
    int kidx = t / C_IN;
    float v = 0.f;
#pragma unroll
    for (int n = 0; n < N_BASES; n++) {
        float wv = w[(((size_t)n * C_OUT + o) * C_IN + i) * 9 + kidx];
        float sg = (wv > 0.f) ? 1.f : ((wv < 0.f) ? -1.f : 0.f);
        v += scales[n] * g_m[n] * sg;
    }
    g_weff[idx * 2 + 0] = v;
    g_weff[idx * 2 + 1] = v;
}

// ================= conv kernel =================
__device__ __forceinline__ void issue_chunk(float* sdst_base, const float* gsrc_base,
                                            int tid) {
    unsigned sdst = (unsigned)__cvta_generic_to_shared(sdst_base) + (unsigned)tid * 16u;
    const float* gsrc = gsrc_base + tid * 4;
#pragma unroll
    for (int j = 0; j < 4; j++) {
        asm volatile("cp.async.cg.shared.global [%0], [%1], 16;" ::"r"(sdst + j * 2048u),
                     "l"(gsrc + j * 512));
    }
    asm volatile("cp.async.commit_group;" ::: "memory");
}

__device__ __forceinline__ void fma_tile(unsigned long long* acc, unsigned long long x0,
                                         unsigned long long x1, unsigned long long x2,
                                         unsigned long long x3, const float* wb) {
    ulonglong2 w01 = *(const ulonglong2*)(wb + 0);
    ulonglong2 w23 = *(const ulonglong2*)(wb + 4);
    ulonglong2 w45 = *(const ulonglong2*)(wb + 8);
    ulonglong2 w67 = *(const ulonglong2*)(wb + 12);
    ffma2(acc[0], x0, w01.x);  ffma2(acc[1], x1, w01.x);
    ffma2(acc[2], x2, w01.x);  ffma2(acc[3], x3, w01.x);
    ffma2(acc[4], x0, w01.y);  ffma2(acc[5], x1, w01.y);
    ffma2(acc[6], x2, w01.y);  ffma2(acc[7], x3, w01.y);
    ffma2(acc[8], x0, w23.x);  ffma2(acc[9], x1, w23.x);
    ffma2(acc[10], x2, w23.x); ffma2(acc[11], x3, w23.x);
    ffma2(acc[12], x0, w23.y); ffma2(acc[13], x1, w23.y);
    ffma2(acc[14], x2, w23.y); ffma2(acc[15], x3, w23.y);
    ffma2(acc[16], x0, w45.x); ffma2(acc[17], x1, w45.x);
    ffma2(acc[18], x2, w45.x); ffma2(acc[19], x3, w45.x);
    ffma2(acc[20], x0, w45.y); ffma2(acc[21], x1, w45.y);
    ffma2(acc[22], x2, w45.y); ffma2(acc[23], x3, w45.y);
    ffma2(acc[24], x0, w67.x); ffma2(acc[25], x1, w67.x);
    ffma2(acc[26], x2, w67.x); ffma2(acc[27], x3, w67.x);
    ffma2(acc[28], x0, w67.y); ffma2(acc[29], x1, w67.y);
    ffma2(acc[30], x2, w67.y); ffma2(acc[31], x3, w67.y);
}

__global__ void __launch_bounds__(128, 4)
conv_kernel(const float* __restrict__ x, float* __restrict__ out) {
    __shared__ __align__(16) float xs[CI_HALF * 10 * XS_STRIDE];  // 30720 B
    __shared__ __align__(16) float ws[2 * WCHUNK];                 // 16384 B

    const int tid = threadIdx.x;
    const int og = tid >> 3;  // 0..15 : o-group (8 outputs each)
    const int pg = tid & 7;   // 0..7  : output row within tile
    const int tx = blockIdx.x, ty = blockIdx.y, b = blockIdx.z;
    const int gy0 = ty * 8 - 1;
    const int gx0 = tx * 8 - 1;

    unsigned long long acc[32];
#pragma unroll
    for (int j = 0; j < 32; j++) acc[j] = 0ULL;

    int buf = 0;
    issue_chunk(ws, g_weff, tid);  // (h=0, kidx=0, ic=0)

#pragma unroll 1
    for (int h = 0; h < 2; h++) {
        // ---- stage x patch for channels [h*64, h*64+64) (pad value = 1.0) ----
        const float* xh = x + ((size_t)b * C_IN + h * CI_HALF) * HW * HW;
#pragma unroll 1
        for (int idx = tid; idx < CI_HALF * 100; idx += 128) {
            int i = idx / 100;
            int rem = idx - i * 100;
            int r = rem / 10;
            int c = rem - r * 10;
            int gy = gy0 + r, gx = gx0 + c;
            float v = 1.0f;
            if ((unsigned)gy < HW && (unsigned)gx < HW)
                v = xh[(i * HW + gy) * HW + gx];
            xs[i * (10 * XS_STRIDE) + r * XS_STRIDE + c] = v;
        }
        // visibility of xs guaranteed by the __syncthreads() before first compute below

#pragma unroll 1
        for (int kidx = 0; kidx < 9; kidx++) {
            const int ky = kidx / 3;
            const int kx = kidx - 3 * ky;
            const float* xb = xs + (pg + ky) * XS_STRIDE + kx;
#pragma unroll 1
            for (int ic = 0; ic < 8; ic++) {
                // prefetch next chunk into the other buffer
                int nic = ic + 1, nk = kidx, nh = h;
                if (nic == 8) { nic = 0; if (++nk == 9) { nk = 0; nh++; } }
                if (nh < 2) {
                    issue_chunk(ws + (buf ^ 1) * WCHUNK,
                                g_weff + ((size_t)(nk * C_IN + nh * CI_HALF + nic * KC)) *
                                             (C_OUT * 2),
                                tid);
                    asm volatile("cp.async.wait_group 1;" ::: "memory");
                } else {
                    asm volatile("cp.async.wait_group 0;" ::: "memory");
                }
                __syncthreads();

                const float* wbase = ws + buf * WCHUNK + og * 16;
                const float* xc = xb + ic * KC * (10 * XS_STRIDE);
                if (kx != 1) {
                    // 8-byte aligned packed loads (kx even)
#pragma unroll
                    for (int kk = 0; kk < KC; kk++) {
                        const float* xr = xc + kk * (10 * XS_STRIDE);
                        unsigned long long x0 = *(const unsigned long long*)(xr + 0);
                        unsigned long long x1 = *(const unsigned long long*)(xr + 2);
                        unsigned long long x2 = *(const unsigned long long*)(xr + 4);
                        unsigned long long x3 = *(const unsigned long long*)(xr + 6);
                        fma_tile(acc, x0, x1, x2, x3, wbase + kk * (C_OUT * 2));
                    }
                } else {
                    // odd offset: scalar loads + pack
#pragma unroll
                    for (int kk = 0; kk < KC; kk++) {
                        const float* xr = xc + kk * (10 * XS_STRIDE);
                        float f0 = xr[0], f1 = xr[1], f2 = xr[2], f3 = xr[3];
                        float f4 = xr[4], f5 = xr[5], f6 = xr[6], f7 = xr[7];
                        unsigned long long x0 = pack2(f0, f1);
                        unsigned long long x1 = pack2(f2, f3);
                        unsigned long long x2 = pack2(f4, f5);
                        unsigned long long x3 = pack2(f6, f7);
                        fma_tile(acc, x0, x1, x2, x3, wbase + kk * (C_OUT * 2));
                    }
                }
                __syncthreads();
                buf ^= 1;
            }
        }
    }

    // ---- epilogue: 8 o x 8 pos per thread ----
    const int oy = ty * 8 + pg;
    const int ox = tx * 8;
#pragma unroll
    for (int oo = 0; oo < 8; oo++) {
        int o = og * 8 + oo;
        float* orow = out + (((size_t)b * C_OUT + o) * HW + oy) * HW + ox;
#pragma unroll
        for (int p = 0; p < 4; p++) {
            float a, bb;
            unpack2(acc[oo * 4 + p], a, bb);
            *(float2*)(orow + 2 * p) = make_float2(a, bb);
        }
    }
}

// ================= launcher =================
extern "C" void kernel_launch(void* const* d_in, const int* in_sizes, int n_in,
                              void* d_out, int out_size) {
    const float* x = (const float*)d_in[0];        // [32,128,56,56]
    const float* w = (const float*)d_in[1];        // [5,128,128,3,3]
    const float* scales = (const float*)d_in[2];   // [5]
    float* out = (float*)d_out;                    // [32,128,56,56]

    mean_abs_kernel<<<N_BASES, 256>>>(w);
    build_weff_kernel<<<(WELEMS + 255) / 256, 256>>>(w, scales);
    conv_kernel<<<dim3(7, 7, BATCH), 128>>>(x, out);
}